// round 7
// baseline (speedup 1.0000x reference)
#include <cuda_runtime.h>
#include <cstdint>
#include <math.h>

#define BATCH 16384
#define DD 4096
#define HH 128
#define EE 64
#define NS 5

#define BM 128
#define BK 32
#define NITER (DD / BK)

#define AS2 72                        // floats per m-row: 32 k * 2 (hi,lo) + 8 pad
#define BS2 264                       // floats per k-row: 128 n * 2 (hi,lo) + 8 pad
#define ASZ (BM * AS2)                // 9216 floats
#define BSZ (BK * BS2)                // 8448 floats
#define STAGEF (ASZ + BSZ)            // 17664 floats
#define SMEM_BYTES (2 * STAGEF * 4)   // 141312 B

__device__ float g_h[(size_t)BATCH * HH];        // 8 MB scratch
__device__ float g_w1s[(size_t)DD * HH * 2];     // 4 MB presplit W1 (hi,lo interleaved)

__device__ __forceinline__ uint32_t smem_u32(const void* p) {
    uint32_t a;
    asm("{ .reg .u64 t; cvta.to.shared.u64 t, %1; cvt.u32.u64 %0, t; }" : "=r"(a) : "l"(p));
    return a;
}
__device__ __forceinline__ void cp16(uint32_t dst, const void* src) {
    asm volatile("cp.async.cg.shared.global [%0], [%1], 16;" :: "r"(dst), "l"(src));
}
#define CP_COMMIT() asm volatile("cp.async.commit_group;" ::: "memory")
#define CP_WAIT0()  asm volatile("cp.async.wait_group 0;" ::: "memory")

__device__ __forceinline__ void mma8(float* c, const uint32_t* a, const uint32_t* b) {
    asm volatile(
        "mma.sync.aligned.m16n8k8.row.col.f32.tf32.tf32.f32 "
        "{%0,%1,%2,%3}, {%4,%5,%6,%7}, {%8,%9}, {%0,%1,%2,%3};"
        : "+f"(c[0]), "+f"(c[1]), "+f"(c[2]), "+f"(c[3])
        : "r"(a[0]), "r"(a[1]), "r"(a[2]), "r"(a[3]), "r"(b[0]), "r"(b[1]));
}
__device__ __forceinline__ float2 splitpair(float v) {
    float hi = __uint_as_float(__float_as_uint(v) & 0xFFFFE000u);  // exact tf32 high
    uint32_t lo;
    asm("cvt.rna.tf32.f32 %0, %1;" : "=r"(lo) : "f"(v - hi));      // unbiased residual
    return make_float2(hi, __uint_as_float(lo));
}
__device__ __forceinline__ uint32_t fu(float v) { return __float_as_uint(v); }

// ---------------------------------------------------------------------------
// prep: W1[k][n] -> g_w1s[(k*HH+n)*2 + {0,1}] = (hi, lo)
// ---------------------------------------------------------------------------
__global__ __launch_bounds__(256) void prep_w1(const float* __restrict__ W1) {
    int i = blockIdx.x * 256 + threadIdx.x;          // over DD*HH/4 float4s
    float4 v = ((const float4*)W1)[i];
    float2 p0 = splitpair(v.x), p1 = splitpair(v.y);
    float2 p2 = splitpair(v.z), p3 = splitpair(v.w);
    float4* o = (float4*)(g_w1s + (size_t)i * 8);
    o[0] = make_float4(p0.x, p0.y, p1.x, p1.y);
    o[1] = make_float4(p2.x, p2.y, p3.x, p3.y);
}

// ---------------------------------------------------------------------------
// GEMM1: h = relu(x @ W1 + b1), mma.sync tf32 3-pass, presplit operands.
// CTA 128x128, BK=32, 8 warps (4m x 2n), warp tile 32x64.
// ---------------------------------------------------------------------------
__device__ __forceinline__ void ldg_x(float4* xv, const float* __restrict__ x,
                                      int rowBase, int k0, int tid) {
#pragma unroll
    for (int l = 0; l < 4; l++) {
        int c = tid + 256 * l;
        int r = c >> 3, q = c & 7;
        xv[l] = *(const float4*)(x + (size_t)(rowBase + r) * DD + k0 + q * 4);
    }
}
__device__ __forceinline__ void sts_a(float* smA, const float4* xv, int tid) {
#pragma unroll
    for (int l = 0; l < 4; l++) {
        int c = tid + 256 * l;
        int r = c >> 3, q = c & 7;
        float2 p0 = splitpair(xv[l].x), p1 = splitpair(xv[l].y);
        float2 p2 = splitpair(xv[l].z), p3 = splitpair(xv[l].w);
        float* dst = smA + r * AS2 + q * 8;
        *(float4*)(dst)     = make_float4(p0.x, p0.y, p1.x, p1.y);
        *(float4*)(dst + 4) = make_float4(p2.x, p2.y, p3.x, p3.y);
    }
}
__device__ __forceinline__ void cpa_b(uint32_t bB, int k0, int tid) {
#pragma unroll
    for (int l = 0; l < 8; l++) {
        int c = tid + 256 * l;               // 0..2047
        int k = c >> 6, off = c & 63;        // k row, 16B chunk
        cp16(bB + k * (BS2 * 4) + off * 16,
             g_w1s + (size_t)(k0 + k) * HH * 2 + off * 4);
    }
}

__global__ __launch_bounds__(256, 1) void gemm1_mma(const float* __restrict__ x,
                                                    const float* __restrict__ b1) {
    extern __shared__ float sm[];
    const int tid = threadIdx.x;
    const int lane = tid & 31;
    const int wid = tid >> 5;
    const int wm = wid & 3;
    const int wn = wid >> 2;
    const int g = lane >> 2, t = lane & 3;
    const int rowBase = blockIdx.x * BM;
    const uint32_t smb = smem_u32(sm);

    float acc[2][8][4];
#pragma unroll
    for (int i = 0; i < 2; i++)
#pragma unroll
        for (int j = 0; j < 8; j++)
#pragma unroll
            for (int r = 0; r < 4; r++) acc[i][j][r] = 0.f;

    // prologue: tile 0 into stage 0
    {
        float4 xv[4];
        ldg_x(xv, x, rowBase, 0, tid);
        sts_a(sm, xv, tid);
        cpa_b(smb + ASZ * 4, 0, tid);
        CP_COMMIT();
    }

    float4 xv[4];
    for (int it = 0; it < NITER; ++it) {
        const int s = it & 1;
        const int p = s ^ 1;
        CP_WAIT0();
        __syncthreads();

        if (it + 1 < NITER) {
            ldg_x(xv, x, rowBase, (it + 1) * BK, tid);
            cpa_b(smb + (uint32_t)((p * STAGEF + ASZ) * 4), (it + 1) * BK, tid);
            CP_COMMIT();
        }

        const float* As = sm + s * STAGEF;
        const float* Bs = As + ASZ;
        const float* aBase = As + (wm * 32 + g) * AS2 + t * 2;
        const float* bBase = Bs + t * BS2 + (wn * 64 + g) * 2;

#pragma unroll
        for (int ks = 0; ks < 4; ks++) {
            const int kb = ks * 8;
            uint32_t aHi[2][4], aLo[2][4];
#pragma unroll
            for (int i = 0; i < 2; i++) {
                const float* ap = aBase + i * 16 * AS2 + kb * 2;
                float2 e0 = *(const float2*)(ap);
                float2 e1 = *(const float2*)(ap + 8 * AS2);
                float2 e2 = *(const float2*)(ap + 8);
                float2 e3 = *(const float2*)(ap + 8 * AS2 + 8);
                aHi[i][0] = fu(e0.x); aLo[i][0] = fu(e0.y);
                aHi[i][1] = fu(e1.x); aLo[i][1] = fu(e1.y);
                aHi[i][2] = fu(e2.x); aLo[i][2] = fu(e2.y);
                aHi[i][3] = fu(e3.x); aLo[i][3] = fu(e3.y);
            }
#pragma unroll
            for (int j = 0; j < 8; j++) {
                const float* bp = bBase + kb * BS2 + j * 16;
                float2 f0 = *(const float2*)(bp);
                float2 f1 = *(const float2*)(bp + 4 * BS2);
                uint32_t bHi[2] = {fu(f0.x), fu(f1.x)};
                uint32_t bLo[2] = {fu(f0.y), fu(f1.y)};
#pragma unroll
                for (int i = 0; i < 2; i++) {
                    mma8(acc[i][j], aHi[i], bHi);
                    mma8(acc[i][j], aHi[i], bLo);
                    mma8(acc[i][j], aLo[i], bHi);
                }
            }
        }

        if (it + 1 < NITER)
            sts_a(sm + p * STAGEF, xv, tid);
    }

    // bias + relu + store
#pragma unroll
    for (int i = 0; i < 2; i++) {
        int r0 = rowBase + wm * 32 + i * 16 + g;
#pragma unroll
        for (int j = 0; j < 8; j++) {
            int col = wn * 64 + j * 8 + 2 * t;
            float2 bv = *(const float2*)&b1[col];
            float2 o0, o1;
            o0.x = fmaxf(acc[i][j][0] + bv.x, 0.f);
            o0.y = fmaxf(acc[i][j][1] + bv.y, 0.f);
            o1.x = fmaxf(acc[i][j][2] + bv.x, 0.f);
            o1.y = fmaxf(acc[i][j][3] + bv.y, 0.f);
            *(float2*)&g_h[(size_t)r0 * HH + col] = o0;
            *(float2*)&g_h[(size_t)(r0 + 8) * HH + col] = o1;
        }
    }
}

// ---------------------------------------------------------------------------
// Epilogue (unchanged, 66 us): one warp per row; shfl-broadcast h + packed
// 5-bit dropout masks. Lane owns experts 2*lane, 2*lane+1.
// ---------------------------------------------------------------------------
__global__ __launch_bounds__(256) void epilogue_kernel(const float* __restrict__ W2,
                                                       const float* __restrict__ b2,
                                                       const float* __restrict__ m1,
                                                       const float* __restrict__ m2,
                                                       float* __restrict__ out,
                                                       int B) {
    __shared__ float ws2[HH * EE];

    const int tid = threadIdx.x;
    const int lane = tid & 31;
    const int warp = tid >> 5;

#pragma unroll
    for (int l = 0; l < 8; l++) {
        int i = (tid + 256 * l) * 4;
        *(float4*)&ws2[i] = *(const float4*)&W2[i];
    }
    __syncthreads();

    const int row = blockIdx.x * 8 + warp;
    const float SCALE = 1.4285714285714286f;

    float hv[4];
    {
        float4 h4 = *(const float4*)&g_h[(size_t)row * HH + lane * 4];
        hv[0] = h4.x * SCALE; hv[1] = h4.y * SCALE;
        hv[2] = h4.z * SCALE; hv[3] = h4.w * SCALE;
    }
    int mv[4] = {0, 0, 0, 0};
#pragma unroll
    for (int s = 0; s < NS; s++) {
        float4 u = *(const float4*)&m1[(size_t)s * B * HH + (size_t)row * HH + lane * 4];
        mv[0] |= (u.x >= 0.3f) << s;
        mv[1] |= (u.y >= 0.3f) << s;
        mv[2] |= (u.z >= 0.3f) << s;
        mv[3] |= (u.w >= 0.3f) << s;
    }

    float a0[NS] = {0, 0, 0, 0, 0}, a1[NS] = {0, 0, 0, 0, 0};
    for (int jo = 0; jo < 4; jo++) {
#pragma unroll
        for (int ji = 0; ji < 32; ji++) {
            int j = jo * 32 + ji;
            float hj = __shfl_sync(0xffffffffu, hv[ji & 3], j >> 2);
            int m5   = __shfl_sync(0xffffffffu, mv[ji & 3], j >> 2);
            float2 w = *(float2*)&ws2[j * EE + lane * 2];
#pragma unroll
            for (int s = 0; s < NS; s++) {
                float hjs = (m5 & (1 << s)) ? hj : 0.f;
                a0[s] = fmaf(hjs, w.x, a0[s]);
                a1[s] = fmaf(hjs, w.y, a1[s]);
            }
        }
    }

    float2 b2v = *(const float2*)&b2[lane * 2];
    float lg0[NS], lg1[NS];
    {
        const float* m2r = m2 + (size_t)row * EE + lane * 2;
#pragma unroll
        for (int s = 0; s < NS; s++) {
            float2 mu = *(const float2*)&m2r[(size_t)s * B * EE];
            lg0[s] = (a0[s] + b2v.x) * ((mu.x >= 0.3f) ? SCALE : 0.f);
            lg1[s] = (a1[s] + b2v.y) * ((mu.y >= 0.3f) ? SCALE : 0.f);
        }
    }

    float ml0 = (lg0[0] + lg0[1] + lg0[2] + lg0[3] + lg0[4]) * 0.2f;
    float ml1 = (lg1[0] + lg1[1] + lg1[2] + lg1[3] + lg1[4]) * 0.2f;
    float mx = fmaxf(ml0, ml1);
#pragma unroll
    for (int off = 16; off; off >>= 1) mx = fmaxf(mx, __shfl_xor_sync(0xffffffffu, mx, off));
    float p0 = expf(ml0 - mx), p1 = expf(ml1 - mx);
    float sm = p0 + p1;
#pragma unroll
    for (int off = 16; off; off >>= 1) sm += __shfl_xor_sync(0xffffffffu, sm, off);
    float pr0 = p0 / sm, pr1 = p1 / sm;

    float ap0[NS], ap1[NS];
#pragma unroll
    for (int s = 0; s < NS; s++) {
        float mxs = fmaxf(lg0[s], lg1[s]);
#pragma unroll
        for (int off = 16; off; off >>= 1) mxs = fmaxf(mxs, __shfl_xor_sync(0xffffffffu, mxs, off));
        float e0 = expf(lg0[s] - mxs), e1 = expf(lg1[s] - mxs);
        float ss = e0 + e1;
#pragma unroll
        for (int off = 16; off; off >>= 1) ss += __shfl_xor_sync(0xffffffffu, ss, off);
        ap0[s] = e0 / ss;
        ap1[s] = e1 / ss;
    }

    float mp0 = (ap0[0] + ap0[1] + ap0[2] + ap0[3] + ap0[4]) * 0.2f;
    float mp1 = (ap1[0] + ap1[1] + ap1[2] + ap1[3] + ap1[4]) * 0.2f;
    float v0 = 0.f, v1 = 0.f;
#pragma unroll
    for (int s = 0; s < NS; s++) {
        float d0 = ap0[s] - mp0, d1 = ap1[s] - mp1;
        v0 = fmaf(d0, d0, v0);
        v1 = fmaf(d1, d1, v1);
    }
    float stds = sqrtf(v0 * 0.25f) + sqrtf(v1 * 0.25f);
#pragma unroll
    for (int off = 16; off; off >>= 1) stds += __shfl_xor_sync(0xffffffffu, stds, off);
    float unc = stds / 64.0f;

    float q0 = pr0, q1 = pr1;
    const int i0 = lane * 2, i1 = lane * 2 + 1;
    float fp[4];
    int fi[4];
#pragma unroll
    for (int k = 0; k < 4; k++) {
        float bp;
        int bi;
        if (q0 >= q1) { bp = q0; bi = i0; }
        else          { bp = q1; bi = i1; }
#pragma unroll
        for (int off = 16; off; off >>= 1) {
            float op = __shfl_xor_sync(0xffffffffu, bp, off);
            int oi = __shfl_xor_sync(0xffffffffu, bi, off);
            if (op > bp || (op == bp && oi < bi)) { bp = op; bi = oi; }
        }
        fp[k] = bp;
        fi[k] = bi;
        if (bi == i0) q0 = -1.f;
        if (bi == i1) q1 = -1.f;
    }

    if (lane == 0) {
        bool uncertain = unc > 0.3f;
        size_t pb = (size_t)4 * B;
        size_t ub = (size_t)8 * B;
        out[(size_t)row * 4 + 0] = (float)fi[0];
        out[(size_t)row * 4 + 1] = (float)fi[1];
        out[(size_t)row * 4 + 2] = uncertain ? (float)fi[2] : -1.0f;
        out[(size_t)row * 4 + 3] = uncertain ? (float)fi[3] : -1.0f;
        out[pb + (size_t)row * 4 + 0] = fp[0];
        out[pb + (size_t)row * 4 + 1] = fp[1];
        out[pb + (size_t)row * 4 + 2] = uncertain ? fp[2] : 0.0f;
        out[pb + (size_t)row * 4 + 3] = uncertain ? fp[3] : 0.0f;
        out[ub + row] = unc;
    }
}

extern "C" void kernel_launch(void* const* d_in, const int* in_sizes, int n_in,
                              void* d_out, int out_size) {
    const float* x  = (const float*)d_in[0];
    const float* W1 = (const float*)d_in[1];
    const float* b1 = (const float*)d_in[2];
    const float* W2 = (const float*)d_in[3];
    const float* b2 = (const float*)d_in[4];
    const float* m1 = (const float*)d_in[5];
    const float* m2 = (const float*)d_in[6];
    float* out = (float*)d_out;

    int B = in_sizes[0] / DD;   // 16384

    cudaFuncSetAttribute(gemm1_mma, cudaFuncAttributeMaxDynamicSharedMemorySize, SMEM_BYTES);

    prep_w1<<<(DD * HH / 4) / 256, 256>>>(W1);
    gemm1_mma<<<B / BM, 256, SMEM_BYTES>>>(x, b1);
    epilogue_kernel<<<B / 8, 256>>>(W2, b2, m1, m2, out, B);
}

// round 8
// speedup vs baseline: 1.2821x; 1.2821x over previous
#include <cuda_runtime.h>
#include <cstdint>
#include <math.h>

#define BATCH 16384
#define DD 4096
#define HH 128
#define EE 64
#define NS 5

#define BM 64
#define BK 32
#define NITER (DD / BK)

// smem strides in floats (padded for conflict-free fragment loads)
#define ASTRIDE 36     // 32 + 4 pad
#define BSTRIDE 136    // 128 + 8 pad
#define ASZ (BM * ASTRIDE)            // 2304 floats
#define BSZ (BK * BSTRIDE)            // 4352 floats
#define STAGE (ASZ + BSZ)             // 6656 floats
#define SMEM_BYTES (2 * STAGE * 4)    // 53248 B

__device__ float g_h[(size_t)BATCH * HH];   // h scratch, 8 MB

__device__ __forceinline__ uint32_t smem_u32(const void* p) {
    uint32_t a;
    asm("{ .reg .u64 t; cvta.to.shared.u64 t, %1; cvt.u32.u64 %0, t; }" : "=r"(a) : "l"(p));
    return a;
}
__device__ __forceinline__ void cp16(uint32_t dst, const void* src) {
    asm volatile("cp.async.cg.shared.global [%0], [%1], 16;" :: "r"(dst), "l"(src));
}
#define CP_COMMIT() asm volatile("cp.async.commit_group;" ::: "memory")
#define CP_WAIT1()  asm volatile("cp.async.wait_group 1;" ::: "memory")
#define CP_WAIT0()  asm volatile("cp.async.wait_group 0;" ::: "memory")

__device__ __forceinline__ void mma8(float* c, const uint32_t* a, const uint32_t* b) {
    asm volatile(
        "mma.sync.aligned.m16n8k8.row.col.f32.tf32.tf32.f32 "
        "{%0,%1,%2,%3}, {%4,%5,%6,%7}, {%8,%9}, {%0,%1,%2,%3};"
        : "+f"(c[0]), "+f"(c[1]), "+f"(c[2]), "+f"(c[3])
        : "r"(a[0]), "r"(a[1]), "r"(a[2]), "r"(a[3]), "r"(b[0]), "r"(b[1]));
}
__device__ __forceinline__ void split_tf32(float v, uint32_t& hi, uint32_t& lo) {
    uint32_t h = __float_as_uint(v) & 0xFFFFE000u;   // exact tf32 high part
    hi = h;
    float l = v - __uint_as_float(h);                // exact residual
    asm("cvt.rna.tf32.f32 %0, %1;" : "=r"(lo) : "f"(l));
}

// ---------------------------------------------------------------------------
// GEMM1: h = relu(x @ W1 + b1) via mma.sync tf32, 3-pass exact split.
// CTA: 64x128, BK=32, 8 warps (2m x 4n), warp tile 32x32, 2 CTAs/SM.
// ---------------------------------------------------------------------------
__device__ __forceinline__ void load_tile(uint32_t smb, int s, int it, int tid,
                                          int rowBase,
                                          const float* __restrict__ x,
                                          const float* __restrict__ W1) {
    int k0 = it * BK;
    uint32_t aB = smb + (uint32_t)(s * STAGE * 4);
    uint32_t bB = aB + ASZ * 4;
#pragma unroll
    for (int l = 0; l < 2; l++) {
        int c = tid + 256 * l;          // 0..511
        int r = c >> 3, q = c & 7;      // row 0..63, quad 0..7
        cp16(aB + r * (ASTRIDE * 4) + q * 16,
             x + (size_t)(rowBase + r) * DD + k0 + q * 4);
    }
#pragma unroll
    for (int l = 0; l < 4; l++) {
        int c = tid + 256 * l;          // 0..1023
        int k = c >> 5, nq = c & 31;    // k 0..31, nquad 0..31
        cp16(bB + k * (BSTRIDE * 4) + nq * 16,
             W1 + (size_t)(k0 + k) * HH + nq * 4);
    }
}

__global__ __launch_bounds__(256, 2) void gemm1_mma(const float* __restrict__ x,
                                                    const float* __restrict__ W1,
                                                    const float* __restrict__ b1) {
    extern __shared__ float sm[];
    const int tid = threadIdx.x;
    const int lane = tid & 31;
    const int wid = tid >> 5;
    const int wm = wid & 1;        // m block: 32*wm
    const int wn = wid >> 1;       // n block: 32*wn
    const int g = lane >> 2, t = lane & 3;
    const int rowBase = blockIdx.x * BM;
    const uint32_t smb = smem_u32(sm);

    float acc[2][4][4];
#pragma unroll
    for (int i = 0; i < 2; i++)
#pragma unroll
        for (int j = 0; j < 4; j++)
#pragma unroll
            for (int r = 0; r < 4; r++) acc[i][j][r] = 0.f;

    load_tile(smb, 0, 0, tid, rowBase, x, W1);
    CP_COMMIT();

    for (int it = 0; it < NITER; ++it) {
        const int s = it & 1;
        if (it + 1 < NITER) {
            load_tile(smb, s ^ 1, it + 1, tid, rowBase, x, W1);
            CP_COMMIT();
            CP_WAIT1();
        } else {
            CP_WAIT0();
        }
        __syncthreads();

        const float* As = sm + s * STAGE;
        const float* Bs = As + ASZ;
#pragma unroll
        for (int ks = 0; ks < 4; ks++) {
            const int kb = ks * 8;
            uint32_t aHi[2][4], aLo[2][4];
#pragma unroll
            for (int i = 0; i < 2; i++) {
                const float* ap = As + (size_t)(wm * 32 + i * 16 + g) * ASTRIDE + kb + t;
                split_tf32(ap[0],               aHi[i][0], aLo[i][0]);
                split_tf32(ap[8 * ASTRIDE],     aHi[i][1], aLo[i][1]);
                split_tf32(ap[4],               aHi[i][2], aLo[i][2]);
                split_tf32(ap[8 * ASTRIDE + 4], aHi[i][3], aLo[i][3]);
            }
            uint32_t bHi[4][2], bLo[4][2];
#pragma unroll
            for (int j = 0; j < 4; j++) {
                const float* bp = Bs + (size_t)(kb + t) * BSTRIDE + wn * 32 + j * 8 + g;
                split_tf32(bp[0],               bHi[j][0], bLo[j][0]);
                split_tf32(bp[4 * BSTRIDE],     bHi[j][1], bLo[j][1]);
            }
#pragma unroll
            for (int i = 0; i < 2; i++)
#pragma unroll
                for (int j = 0; j < 4; j++) {
                    mma8(acc[i][j], aHi[i], bHi[j]);
                    mma8(acc[i][j], aHi[i], bLo[j]);
                    mma8(acc[i][j], aLo[i], bHi[j]);
                }
        }
        __syncthreads();
    }

    // bias + relu + store
#pragma unroll
    for (int i = 0; i < 2; i++) {
        int r0 = rowBase + wm * 32 + i * 16 + g;
#pragma unroll
        for (int j = 0; j < 4; j++) {
            int col = wn * 32 + j * 8 + 2 * t;
            float2 bv = *(const float2*)&b1[col];
            float2 o0, o1;
            o0.x = fmaxf(acc[i][j][0] + bv.x, 0.f);
            o0.y = fmaxf(acc[i][j][1] + bv.y, 0.f);
            o1.x = fmaxf(acc[i][j][2] + bv.x, 0.f);
            o1.y = fmaxf(acc[i][j][3] + bv.y, 0.f);
            *(float2*)&g_h[(size_t)r0 * HH + col] = o0;
            *(float2*)&g_h[(size_t)(r0 + 8) * HH + col] = o1;
        }
    }
}

// ---------------------------------------------------------------------------
// Epilogue (unchanged, 66 us): one warp per row; shfl-broadcast h + packed
// 5-bit dropout masks. Lane owns experts 2*lane, 2*lane+1.
// ---------------------------------------------------------------------------
__global__ __launch_bounds__(256) void epilogue_kernel(const float* __restrict__ W2,
                                                       const float* __restrict__ b2,
                                                       const float* __restrict__ m1,
                                                       const float* __restrict__ m2,
                                                       float* __restrict__ out,
                                                       int B) {
    __shared__ float ws2[HH * EE];

    const int tid = threadIdx.x;
    const int lane = tid & 31;
    const int warp = tid >> 5;

#pragma unroll
    for (int l = 0; l < 8; l++) {
        int i = (tid + 256 * l) * 4;
        *(float4*)&ws2[i] = *(const float4*)&W2[i];
    }
    __syncthreads();

    const int row = blockIdx.x * 8 + warp;
    const float SCALE = 1.4285714285714286f;

    float hv[4];
    {
        float4 h4 = *(const float4*)&g_h[(size_t)row * HH + lane * 4];
        hv[0] = h4.x * SCALE; hv[1] = h4.y * SCALE;
        hv[2] = h4.z * SCALE; hv[3] = h4.w * SCALE;
    }
    int mv[4] = {0, 0, 0, 0};
#pragma unroll
    for (int s = 0; s < NS; s++) {
        float4 u = *(const float4*)&m1[(size_t)s * B * HH + (size_t)row * HH + lane * 4];
        mv[0] |= (u.x >= 0.3f) << s;
        mv[1] |= (u.y >= 0.3f) << s;
        mv[2] |= (u.z >= 0.3f) << s;
        mv[3] |= (u.w >= 0.3f) << s;
    }

    float a0[NS] = {0, 0, 0, 0, 0}, a1[NS] = {0, 0, 0, 0, 0};
    for (int jo = 0; jo < 4; jo++) {
#pragma unroll
        for (int ji = 0; ji < 32; ji++) {
            int j = jo * 32 + ji;
            float hj = __shfl_sync(0xffffffffu, hv[ji & 3], j >> 2);
            int m5   = __shfl_sync(0xffffffffu, mv[ji & 3], j >> 2);
            float2 w = *(float2*)&ws2[j * EE + lane * 2];
#pragma unroll
            for (int s = 0; s < NS; s++) {
                float hjs = (m5 & (1 << s)) ? hj : 0.f;
                a0[s] = fmaf(hjs, w.x, a0[s]);
                a1[s] = fmaf(hjs, w.y, a1[s]);
            }
        }
    }

    float2 b2v = *(const float2*)&b2[lane * 2];
    float lg0[NS], lg1[NS];
    {
        const float* m2r = m2 + (size_t)row * EE + lane * 2;
#pragma unroll
        for (int s = 0; s < NS; s++) {
            float2 mu = *(const float2*)&m2r[(size_t)s * B * EE];
            lg0[s] = (a0[s] + b2v.x) * ((mu.x >= 0.3f) ? SCALE : 0.f);
            lg1[s] = (a1[s] + b2v.y) * ((mu.y >= 0.3f) ? SCALE : 0.f);
        }
    }

    float ml0 = (lg0[0] + lg0[1] + lg0[2] + lg0[3] + lg0[4]) * 0.2f;
    float ml1 = (lg1[0] + lg1[1] + lg1[2] + lg1[3] + lg1[4]) * 0.2f;
    float mx = fmaxf(ml0, ml1);
#pragma unroll
    for (int off = 16; off; off >>= 1) mx = fmaxf(mx, __shfl_xor_sync(0xffffffffu, mx, off));
    float p0 = expf(ml0 - mx), p1 = expf(ml1 - mx);
    float sm = p0 + p1;
#pragma unroll
    for (int off = 16; off; off >>= 1) sm += __shfl_xor_sync(0xffffffffu, sm, off);
    float pr0 = p0 / sm, pr1 = p1 / sm;

    float ap0[NS], ap1[NS];
#pragma unroll
    for (int s = 0; s < NS; s++) {
        float mxs = fmaxf(lg0[s], lg1[s]);
#pragma unroll
        for (int off = 16; off; off >>= 1) mxs = fmaxf(mxs, __shfl_xor_sync(0xffffffffu, mxs, off));
        float e0 = expf(lg0[s] - mxs), e1 = expf(lg1[s] - mxs);
        float ss = e0 + e1;
#pragma unroll
        for (int off = 16; off; off >>= 1) ss += __shfl_xor_sync(0xffffffffu, ss, off);
        ap0[s] = e0 / ss;
        ap1[s] = e1 / ss;
    }

    float mp0 = (ap0[0] + ap0[1] + ap0[2] + ap0[3] + ap0[4]) * 0.2f;
    float mp1 = (ap1[0] + ap1[1] + ap1[2] + ap1[3] + ap1[4]) * 0.2f;
    float v0 = 0.f, v1 = 0.f;
#pragma unroll
    for (int s = 0; s < NS; s++) {
        float d0 = ap0[s] - mp0, d1 = ap1[s] - mp1;
        v0 = fmaf(d0, d0, v0);
        v1 = fmaf(d1, d1, v1);
    }
    float stds = sqrtf(v0 * 0.25f) + sqrtf(v1 * 0.25f);
#pragma unroll
    for (int off = 16; off; off >>= 1) stds += __shfl_xor_sync(0xffffffffu, stds, off);
    float unc = stds / 64.0f;

    float q0 = pr0, q1 = pr1;
    const int i0 = lane * 2, i1 = lane * 2 + 1;
    float fp[4];
    int fi[4];
#pragma unroll
    for (int k = 0; k < 4; k++) {
        float bp;
        int bi;
        if (q0 >= q1) { bp = q0; bi = i0; }
        else          { bp = q1; bi = i1; }
#pragma unroll
        for (int off = 16; off; off >>= 1) {
            float op = __shfl_xor_sync(0xffffffffu, bp, off);
            int oi = __shfl_xor_sync(0xffffffffu, bi, off);
            if (op > bp || (op == bp && oi < bi)) { bp = op; bi = oi; }
        }
        fp[k] = bp;
        fi[k] = bi;
        if (bi == i0) q0 = -1.f;
        if (bi == i1) q1 = -1.f;
    }

    if (lane == 0) {
        bool uncertain = unc > 0.3f;
        size_t pb = (size_t)4 * B;
        size_t ub = (size_t)8 * B;
        out[(size_t)row * 4 + 0] = (float)fi[0];
        out[(size_t)row * 4 + 1] = (float)fi[1];
        out[(size_t)row * 4 + 2] = uncertain ? (float)fi[2] : -1.0f;
        out[(size_t)row * 4 + 3] = uncertain ? (float)fi[3] : -1.0f;
        out[pb + (size_t)row * 4 + 0] = fp[0];
        out[pb + (size_t)row * 4 + 1] = fp[1];
        out[pb + (size_t)row * 4 + 2] = uncertain ? fp[2] : 0.0f;
        out[pb + (size_t)row * 4 + 3] = uncertain ? fp[3] : 0.0f;
        out[ub + row] = unc;
    }
}

extern "C" void kernel_launch(void* const* d_in, const int* in_sizes, int n_in,
                              void* d_out, int out_size) {
    const float* x  = (const float*)d_in[0];
    const float* W1 = (const float*)d_in[1];
    const float* b1 = (const float*)d_in[2];
    const float* W2 = (const float*)d_in[3];
    const float* b2 = (const float*)d_in[4];
    const float* m1 = (const float*)d_in[5];
    const float* m2 = (const float*)d_in[6];
    float* out = (float*)d_out;

    int B = in_sizes[0] / DD;   // 16384

    cudaFuncSetAttribute(gemm1_mma, cudaFuncAttributeMaxDynamicSharedMemorySize, SMEM_BYTES);

    gemm1_mma<<<B / BM, 256, SMEM_BYTES>>>(x, W1, b1);
    epilogue_kernel<<<B / 8, 256>>>(W2, b2, m1, m2, out, B);
}

// round 9
// speedup vs baseline: 1.7390x; 1.3563x over previous
#include <cuda_runtime.h>
#include <cuda_fp16.h>
#include <cstdint>
#include <math.h>

#define BATCH 16384
#define DD 4096
#define HH 128
#define EE 64
#define NS 5

#define BM 64
#define BK 32
#define NITER (DD / BK)

#define PADK 40                        // halves per k-row (32 + 8 pad)
#define AHI_OFF 0
#define ALO_OFF (64 * PADK)            // 2560
#define BHI_OFF (2 * 64 * PADK)        // 5120
#define BLO_OFF (BHI_OFF + 128 * PADK) // 10240
#define STAGEH (BLO_OFF + 128 * PADK)  // 15360 halves
#define SMEM_BYTES (2 * STAGEH * 2)    // 61440 B

__device__ float g_h[(size_t)BATCH * HH];        // 8 MB scratch
__device__ __half g_w1t_hi[(size_t)HH * DD];     // 1 MB, W1^T * 64, fp16 hi
__device__ __half g_w1t_lo[(size_t)HH * DD];     // 1 MB, residual fp16

__device__ __forceinline__ uint32_t smem_u32(const void* p) {
    uint32_t a;
    asm("{ .reg .u64 t; cvta.to.shared.u64 t, %1; cvt.u32.u64 %0, t; }" : "=r"(a) : "l"(p));
    return a;
}
__device__ __forceinline__ void cp16(uint32_t dst, const void* src) {
    asm volatile("cp.async.cg.shared.global [%0], [%1], 16;" :: "r"(dst), "l"(src));
}
#define CP_COMMIT() asm volatile("cp.async.commit_group;" ::: "memory")
#define CP_WAIT1()  asm volatile("cp.async.wait_group 1;" ::: "memory")
#define CP_WAIT0()  asm volatile("cp.async.wait_group 0;" ::: "memory")

__device__ __forceinline__ void mma16(float* c, const uint32_t* a, const uint32_t* b) {
    asm volatile(
        "mma.sync.aligned.m16n8k16.row.col.f32.f16.f16.f32 "
        "{%0,%1,%2,%3}, {%4,%5,%6,%7}, {%8,%9}, {%0,%1,%2,%3};"
        : "+f"(c[0]), "+f"(c[1]), "+f"(c[2]), "+f"(c[3])
        : "r"(a[0]), "r"(a[1]), "r"(a[2]), "r"(a[3]), "r"(b[0]), "r"(b[1]));
}
__device__ __forceinline__ uint32_t h2u(__half2 h) { return *(uint32_t*)&h; }

// ---------------------------------------------------------------------------
// prep: W1[k][n] -> g_w1t_{hi,lo}[n][k] fp16, scaled by 64 (transpose + split)
// ---------------------------------------------------------------------------
__global__ __launch_bounds__(256) void prep_w1(const float* __restrict__ W1) {
    __shared__ float t[32][33];
    int kb = blockIdx.x * 32, nb = blockIdx.y * 32;
    int c = threadIdx.x & 31, r0 = threadIdx.x >> 5;
#pragma unroll
    for (int rr = 0; rr < 32; rr += 8)
        t[r0 + rr][c] = W1[(size_t)(kb + r0 + rr) * HH + nb + c];
    __syncthreads();
#pragma unroll
    for (int rr = 0; rr < 32; rr += 8) {
        int n = nb + r0 + rr, k = kb + c;
        float v = t[c][r0 + rr] * 64.0f;
        __half hi = __float2half_rn(v);
        __half lo = __float2half_rn(v - __half2float(hi));
        g_w1t_hi[(size_t)n * DD + k] = hi;
        g_w1t_lo[(size_t)n * DD + k] = lo;
    }
}

// ---------------------------------------------------------------------------
// GEMM1: h = relu((x*64W1)/64 + b1) via mma.sync m16n8k16 fp16, 3-pass split.
// CTA: 64x128, BK=32, 8 warps (2m x 4n), warp tile 32x32, 2 CTAs/SM.
// ---------------------------------------------------------------------------
__device__ __forceinline__ void ldg_x(float4* xv, const float* __restrict__ x,
                                      int rowBase, int k0, int tid) {
#pragma unroll
    for (int l = 0; l < 2; l++) {
        int c = tid + 256 * l;
        int r = c >> 3, q = c & 7;
        xv[l] = *(const float4*)(x + (size_t)(rowBase + r) * DD + k0 + q * 4);
    }
}
__device__ __forceinline__ void sts_a(__half* st, const float4* xv, int tid) {
#pragma unroll
    for (int l = 0; l < 2; l++) {
        int c = tid + 256 * l;
        int r = c >> 3, q = c & 7;
        float4 v = xv[l];
        __half h0 = __float2half_rn(v.x), h1 = __float2half_rn(v.y);
        __half h2 = __float2half_rn(v.z), h3 = __float2half_rn(v.w);
        __half2 hi01 = __halves2half2(h0, h1), hi23 = __halves2half2(h2, h3);
        __half2 lo01 = __halves2half2(__float2half_rn(v.x - __half2float(h0)),
                                      __float2half_rn(v.y - __half2float(h1)));
        __half2 lo23 = __halves2half2(__float2half_rn(v.z - __half2float(h2)),
                                      __float2half_rn(v.w - __half2float(h3)));
        *(uint2*)(st + AHI_OFF + r * PADK + q * 4) = make_uint2(h2u(hi01), h2u(hi23));
        *(uint2*)(st + ALO_OFF + r * PADK + q * 4) = make_uint2(h2u(lo01), h2u(lo23));
    }
}
__device__ __forceinline__ void cpa_b(uint32_t stB, int k0, int tid) {
#pragma unroll
    for (int l = 0; l < 4; l++) {
        int c = tid + 256 * l;               // 0..1023
        int comp = c >> 9;                   // 0=hi, 1=lo
        int cc = c & 511;
        int n = cc >> 2, ch = cc & 3;        // n row, 16B chunk (8 halves)
        const __half* src = (comp ? g_w1t_lo : g_w1t_hi) + (size_t)n * DD + k0 + ch * 8;
        uint32_t dst = stB + (uint32_t)(((comp ? BLO_OFF : BHI_OFF) + n * PADK + ch * 8) * 2);
        cp16(dst, src);
    }
}

__global__ __launch_bounds__(256, 2) void gemm1_mma(const float* __restrict__ x,
                                                    const float* __restrict__ b1) {
    extern __shared__ __half smh[];
    const int tid = threadIdx.x;
    const int lane = tid & 31;
    const int wid = tid >> 5;
    const int wm = wid & 1;        // m block: 32*wm
    const int wn = wid >> 1;       // n block: 32*wn
    const int g = lane >> 2, t = lane & 3;
    const int rowBase = blockIdx.x * BM;
    const uint32_t smb = smem_u32(smh);

    float acc[2][4][4];
#pragma unroll
    for (int i = 0; i < 2; i++)
#pragma unroll
        for (int j = 0; j < 4; j++)
#pragma unroll
            for (int r = 0; r < 4; r++) acc[i][j][r] = 0.f;

    // prologue: tile 0 into stage 0
    {
        float4 xv0[2];
        cpa_b(smb, 0, tid);
        CP_COMMIT();
        ldg_x(xv0, x, rowBase, 0, tid);
        sts_a(smh, xv0, tid);
    }

    float4 xv[2];
    for (int it = 0; it < NITER; ++it) {
        const int s = it & 1;
        const int p = s ^ 1;
        __syncthreads();                       // stage s fully written (A sts + B cp)
        if (it + 1 < NITER) {
            cpa_b(smb + (uint32_t)(p * STAGEH * 2), (it + 1) * BK, tid);
            CP_COMMIT();
            CP_WAIT1();                        // B(s) guaranteed complete
            ldg_x(xv, x, rowBase, (it + 1) * BK, tid);
        } else {
            CP_WAIT0();
        }

        const __half* St = smh + s * STAGEH;
        const __half* Ahi = St + AHI_OFF;
        const __half* Alo = St + ALO_OFF;
        const __half* Bhi = St + BHI_OFF;
        const __half* Blo = St + BLO_OFF;
        const int aRow0 = wm * 32 + g;
        const int bRow0 = wn * 32 + g;

#pragma unroll
        for (int ks = 0; ks < 2; ks++) {
            const int ak = ks * 16 + 2 * t;
            uint32_t ah[2][4], al[2][4];
#pragma unroll
            for (int i = 0; i < 2; i++) {
                const __half* pr = Ahi + (aRow0 + i * 16) * PADK + ak;
                ah[i][0] = *(const uint32_t*)(pr);
                ah[i][1] = *(const uint32_t*)(pr + 8 * PADK);
                ah[i][2] = *(const uint32_t*)(pr + 8);
                ah[i][3] = *(const uint32_t*)(pr + 8 * PADK + 8);
                const __half* pl = Alo + (aRow0 + i * 16) * PADK + ak;
                al[i][0] = *(const uint32_t*)(pl);
                al[i][1] = *(const uint32_t*)(pl + 8 * PADK);
                al[i][2] = *(const uint32_t*)(pl + 8);
                al[i][3] = *(const uint32_t*)(pl + 8 * PADK + 8);
            }
#pragma unroll
            for (int j = 0; j < 4; j++) {
                const __half* pb = Bhi + (bRow0 + j * 8) * PADK + ak;
                uint32_t bh[2] = {*(const uint32_t*)(pb), *(const uint32_t*)(pb + 8)};
                const __half* pc = Blo + (bRow0 + j * 8) * PADK + ak;
                uint32_t bl[2] = {*(const uint32_t*)(pc), *(const uint32_t*)(pc + 8)};
#pragma unroll
                for (int i = 0; i < 2; i++) {
                    mma16(acc[i][j], ah[i], bh);
                    mma16(acc[i][j], ah[i], bl);
                    mma16(acc[i][j], al[i], bh);
                }
            }
        }

        if (it + 1 < NITER)
            sts_a(smh + p * STAGEH, xv, tid);
    }

    // unscale + bias + relu + store
    const float INV = 0.015625f;   // 1/64 exact
#pragma unroll
    for (int i = 0; i < 2; i++) {
        int r0 = rowBase + wm * 32 + i * 16 + g;
#pragma unroll
        for (int j = 0; j < 4; j++) {
            int col = wn * 32 + j * 8 + 2 * t;
            float2 bv = *(const float2*)&b1[col];
            float2 o0, o1;
            o0.x = fmaxf(fmaf(acc[i][j][0], INV, bv.x), 0.f);
            o0.y = fmaxf(fmaf(acc[i][j][1], INV, bv.y), 0.f);
            o1.x = fmaxf(fmaf(acc[i][j][2], INV, bv.x), 0.f);
            o1.y = fmaxf(fmaf(acc[i][j][3], INV, bv.y), 0.f);
            *(float2*)&g_h[(size_t)r0 * HH + col] = o0;
            *(float2*)&g_h[(size_t)(r0 + 8) * HH + col] = o1;
        }
    }
}

// ---------------------------------------------------------------------------
// Epilogue (unchanged, 66 us): one warp per row; shfl-broadcast h + packed
// 5-bit dropout masks. Lane owns experts 2*lane, 2*lane+1.
// ---------------------------------------------------------------------------
__global__ __launch_bounds__(256) void epilogue_kernel(const float* __restrict__ W2,
                                                       const float* __restrict__ b2,
                                                       const float* __restrict__ m1,
                                                       const float* __restrict__ m2,
                                                       float* __restrict__ out,
                                                       int B) {
    __shared__ float ws2[HH * EE];

    const int tid = threadIdx.x;
    const int lane = tid & 31;
    const int warp = tid >> 5;

#pragma unroll
    for (int l = 0; l < 8; l++) {
        int i = (tid + 256 * l) * 4;
        *(float4*)&ws2[i] = *(const float4*)&W2[i];
    }
    __syncthreads();

    const int row = blockIdx.x * 8 + warp;
    const float SCALE = 1.4285714285714286f;

    float hv[4];
    {
        float4 h4 = *(const float4*)&g_h[(size_t)row * HH + lane * 4];
        hv[0] = h4.x * SCALE; hv[1] = h4.y * SCALE;
        hv[2] = h4.z * SCALE; hv[3] = h4.w * SCALE;
    }
    int mv[4] = {0, 0, 0, 0};
#pragma unroll
    for (int s = 0; s < NS; s++) {
        float4 u = *(const float4*)&m1[(size_t)s * B * HH + (size_t)row * HH + lane * 4];
        mv[0] |= (u.x >= 0.3f) << s;
        mv[1] |= (u.y >= 0.3f) << s;
        mv[2] |= (u.z >= 0.3f) << s;
        mv[3] |= (u.w >= 0.3f) << s;
    }

    float a0[NS] = {0, 0, 0, 0, 0}, a1[NS] = {0, 0, 0, 0, 0};
    for (int jo = 0; jo < 4; jo++) {
#pragma unroll
        for (int ji = 0; ji < 32; ji++) {
            int j = jo * 32 + ji;
            float hj = __shfl_sync(0xffffffffu, hv[ji & 3], j >> 2);
            int m5   = __shfl_sync(0xffffffffu, mv[ji & 3], j >> 2);
            float2 w = *(float2*)&ws2[j * EE + lane * 2];
#pragma unroll
            for (int s = 0; s < NS; s++) {
                float hjs = (m5 & (1 << s)) ? hj : 0.f;
                a0[s] = fmaf(hjs, w.x, a0[s]);
                a1[s] = fmaf(hjs, w.y, a1[s]);
            }
        }
    }

    float2 b2v = *(const float2*)&b2[lane * 2];
    float lg0[NS], lg1[NS];
    {
        const float* m2r = m2 + (size_t)row * EE + lane * 2;
#pragma unroll
        for (int s = 0; s < NS; s++) {
            float2 mu = *(const float2*)&m2r[(size_t)s * B * EE];
            lg0[s] = (a0[s] + b2v.x) * ((mu.x >= 0.3f) ? SCALE : 0.f);
            lg1[s] = (a1[s] + b2v.y) * ((mu.y >= 0.3f) ? SCALE : 0.f);
        }
    }

    float ml0 = (lg0[0] + lg0[1] + lg0[2] + lg0[3] + lg0[4]) * 0.2f;
    float ml1 = (lg1[0] + lg1[1] + lg1[2] + lg1[3] + lg1[4]) * 0.2f;
    float mx = fmaxf(ml0, ml1);
#pragma unroll
    for (int off = 16; off; off >>= 1) mx = fmaxf(mx, __shfl_xor_sync(0xffffffffu, mx, off));
    float p0 = expf(ml0 - mx), p1 = expf(ml1 - mx);
    float sm = p0 + p1;
#pragma unroll
    for (int off = 16; off; off >>= 1) sm += __shfl_xor_sync(0xffffffffu, sm, off);
    float pr0 = p0 / sm, pr1 = p1 / sm;

    float ap0[NS], ap1[NS];
#pragma unroll
    for (int s = 0; s < NS; s++) {
        float mxs = fmaxf(lg0[s], lg1[s]);
#pragma unroll
        for (int off = 16; off; off >>= 1) mxs = fmaxf(mxs, __shfl_xor_sync(0xffffffffu, mxs, off));
        float e0 = expf(lg0[s] - mxs), e1 = expf(lg1[s] - mxs);
        float ss = e0 + e1;
#pragma unroll
        for (int off = 16; off; off >>= 1) ss += __shfl_xor_sync(0xffffffffu, ss, off);
        ap0[s] = e0 / ss;
        ap1[s] = e1 / ss;
    }

    float mp0 = (ap0[0] + ap0[1] + ap0[2] + ap0[3] + ap0[4]) * 0.2f;
    float mp1 = (ap1[0] + ap1[1] + ap1[2] + ap1[3] + ap1[4]) * 0.2f;
    float v0 = 0.f, v1 = 0.f;
#pragma unroll
    for (int s = 0; s < NS; s++) {
        float d0 = ap0[s] - mp0, d1 = ap1[s] - mp1;
        v0 = fmaf(d0, d0, v0);
        v1 = fmaf(d1, d1, v1);
    }
    float stds = sqrtf(v0 * 0.25f) + sqrtf(v1 * 0.25f);
#pragma unroll
    for (int off = 16; off; off >>= 1) stds += __shfl_xor_sync(0xffffffffu, stds, off);
    float unc = stds / 64.0f;

    float q0 = pr0, q1 = pr1;
    const int i0 = lane * 2, i1 = lane * 2 + 1;
    float fp[4];
    int fi[4];
#pragma unroll
    for (int k = 0; k < 4; k++) {
        float bp;
        int bi;
        if (q0 >= q1) { bp = q0; bi = i0; }
        else          { bp = q1; bi = i1; }
#pragma unroll
        for (int off = 16; off; off >>= 1) {
            float op = __shfl_xor_sync(0xffffffffu, bp, off);
            int oi = __shfl_xor_sync(0xffffffffu, bi, off);
            if (op > bp || (op == bp && oi < bi)) { bp = op; bi = oi; }
        }
        fp[k] = bp;
        fi[k] = bi;
        if (bi == i0) q0 = -1.f;
        if (bi == i1) q1 = -1.f;
    }

    if (lane == 0) {
        bool uncertain = unc > 0.3f;
        size_t pb = (size_t)4 * B;
        size_t ub = (size_t)8 * B;
        out[(size_t)row * 4 + 0] = (float)fi[0];
        out[(size_t)row * 4 + 1] = (float)fi[1];
        out[(size_t)row * 4 + 2] = uncertain ? (float)fi[2] : -1.0f;
        out[(size_t)row * 4 + 3] = uncertain ? (float)fi[3] : -1.0f;
        out[pb + (size_t)row * 4 + 0] = fp[0];
        out[pb + (size_t)row * 4 + 1] = fp[1];
        out[pb + (size_t)row * 4 + 2] = uncertain ? fp[2] : 0.0f;
        out[pb + (size_t)row * 4 + 3] = uncertain ? fp[3] : 0.0f;
        out[ub + row] = unc;
    }
}

extern "C" void kernel_launch(void* const* d_in, const int* in_sizes, int n_in,
                              void* d_out, int out_size) {
    const float* x  = (const float*)d_in[0];
    const float* W1 = (const float*)d_in[1];
    const float* b1 = (const float*)d_in[2];
    const float* W2 = (const float*)d_in[3];
    const float* b2 = (const float*)d_in[4];
    const float* m1 = (const float*)d_in[5];
    const float* m2 = (const float*)d_in[6];
    float* out = (float*)d_out;

    int B = in_sizes[0] / DD;   // 16384

    cudaFuncSetAttribute(gemm1_mma, cudaFuncAttributeMaxDynamicSharedMemorySize, SMEM_BYTES);

    prep_w1<<<dim3(DD / 32, HH / 32), 256>>>(W1);
    gemm1_mma<<<B / BM, 256, SMEM_BYTES>>>(x, b1);
    epilogue_kernel<<<B / 8, 256>>>(W2, b2, m1, m2, out, B);
}